// round 7
// baseline (speedup 1.0000x reference)
#include <cuda_runtime.h>
#include <cstdint>

#define N_LEVELS 16
#define TABLE_SIZE (1u << 19)
#define TMASK (TABLE_SIZE - 1u)
#define P1 2654435761u
#define P2 805459861u
#define BLOCK 128
#define MAXN 2000000
#define GBITS 6
#define GRES (1 << GBITS)            // 64 cells per dim
#define NCELLS (GRES * GRES * GRES)  // 262144
#define SCAN_T 1024
#define CPT (NCELLS / SCAN_T)        // 256 cells per scan thread

using ull = unsigned long long;

__device__ __forceinline__ ull pack2(float lo, float hi) {
    ull r; asm("mov.b64 %0, {%1, %2};" : "=l"(r) : "f"(lo), "f"(hi)); return r;
}
__device__ __forceinline__ void unpack2(ull v, float& lo, float& hi) {
    asm("mov.b64 {%0, %1}, %2;" : "=f"(lo), "=f"(hi) : "l"(v));
}
__device__ __forceinline__ ull fma2(ull a, ull b, ull c) {
    ull d; asm("fma.rn.f32x2 %0, %1, %2, %3;" : "=l"(d) : "l"(a), "l"(b), "l"(c)); return d;
}

// ---- static scratch (no allocation) ----
__device__ int    d_hist[NCELLS];
__device__ int    d_offs[NCELLS];
__device__ float4 d_xs[MAXN];   // bucket-sorted: (x01, y01, z01, bits(orig_idx))

// expand 6 bits so there are 2 zero bits between each (Morton part1by2)
__device__ __forceinline__ unsigned part1by2(unsigned v) {
    v &= 0x3FFu;
    v = (v | (v << 16)) & 0x030000FFu;
    v = (v | (v << 8))  & 0x0300F00Fu;
    v = (v | (v << 4))  & 0x030C30C3u;
    v = (v | (v << 2))  & 0x09249249u;
    return v;
}

__device__ __forceinline__ int cell_of(float x0, float x1, float x2) {
    unsigned cx = min(GRES - 1, (int)(x0 * (float)GRES));
    unsigned cy = min(GRES - 1, (int)(x1 * (float)GRES));
    unsigned cz = min(GRES - 1, (int)(x2 * (float)GRES));
    return (int)((part1by2(cx) << 2) | (part1by2(cy) << 1) | part1by2(cz));
}

__global__ void k_zero() {
    int i = blockIdx.x * blockDim.x + threadIdx.x;
    if (i < NCELLS) d_hist[i] = 0;
}

__global__ void k_hist(const float* __restrict__ x, int n) {
    int i = blockIdx.x * blockDim.x + threadIdx.x;
    if (i >= n) return;
    float x0 = x[3 * i + 0] * 0.5f + 0.5f;
    float x1 = x[3 * i + 1] * 0.5f + 0.5f;
    float x2 = x[3 * i + 2] * 0.5f + 0.5f;
    atomicAdd(&d_hist[cell_of(x0, x1, x2)], 1);
}

// exclusive scan of d_hist (NCELLS) -> d_offs; one block, CPT cells/thread,
// two passes over the (L2-hot) histogram.
__global__ void k_scan() {
    __shared__ int sc[SCAN_T];
    const int t = threadIdx.x;
    const int base = t * CPT;
    int s = 0;
    for (int k = 0; k < CPT; k++) s += d_hist[base + k];
    sc[t] = s;
    __syncthreads();
    for (int d = 1; d < SCAN_T; d <<= 1) {
        int v = (t >= d) ? sc[t - d] : 0;
        __syncthreads();
        sc[t] += v;
        __syncthreads();
    }
    int run = sc[t] - s;   // exclusive prefix of this thread's chunk
    for (int k = 0; k < CPT; k++) { d_offs[base + k] = run; run += d_hist[base + k]; }
}

__global__ void k_scatter(const float* __restrict__ x, int n) {
    int i = blockIdx.x * blockDim.x + threadIdx.x;
    if (i >= n) return;
    float x0 = x[3 * i + 0] * 0.5f + 0.5f;
    float x1 = x[3 * i + 1] * 0.5f + 0.5f;
    float x2 = x[3 * i + 2] * 0.5f + 0.5f;
    int pos = atomicAdd(&d_offs[cell_of(x0, x1, x2)], 1);
    d_xs[pos] = make_float4(x0, x1, x2, __int_as_float(i));
}

__global__ __launch_bounds__(BLOCK, 4)
void hashgrid_mlp_kernel(const float* __restrict__ tables,
                         const float* __restrict__ resolutions,
                         const float* __restrict__ W1, const float* __restrict__ b1,
                         const float* __restrict__ W2, const float* __restrict__ b2,
                         const float* __restrict__ W3, const float* __restrict__ b3,
                         float* __restrict__ out, int n)
{
    __shared__ __align__(16) float sW1[32 * 64];
    __shared__ __align__(16) float sW2[64 * 64];
    __shared__ __align__(16) float sB1[64];
    __shared__ __align__(16) float sB2[64];
    __shared__ __align__(16) float sW3[64];
    __shared__ float sRes[16];
    __shared__ float sB3;

    const int tid = threadIdx.x;
    for (int i = tid; i < 32 * 64; i += BLOCK) sW1[i] = W1[i];
    for (int i = tid; i < 64 * 64; i += BLOCK) sW2[i] = W2[i];
    if (tid < 64) { sB1[tid] = b1[tid]; sB2[tid] = b2[tid]; sW3[tid] = W3[tid]; }
    if (tid < 16) sRes[tid] = resolutions[tid];
    if (tid == 0) sB3 = b3[0];
    __syncthreads();

    const int p = blockIdx.x * BLOCK + tid;
    if (p >= n) return;

    const float4 xi = d_xs[p];            // coalesced; Morton-bucket-sorted point
    const float x0 = xi.x, x1 = xi.y, x2 = xi.z;
    const int oidx = __float_as_int(xi.w);

    float a[2 * N_LEVELS];

    #pragma unroll
    for (int L = 0; L < N_LEVELS; L++) {
        const float r = sRes[L];
        const float px = x0 * r, py = x1 * r, pz = x2 * r;
        const float fx = floorf(px), fy = floorf(py), fz = floorf(pz);
        const float wx = px - fx, wy = py - fy, wz = pz - fz;
        const unsigned cx = (unsigned)fx, cy = (unsigned)fy, cz = (unsigned)fz;

        const unsigned hx0 = cx,        hx1 = cx + 1u;
        const unsigned hy0 = cy * P1,   hy1 = (cy + 1u) * P1;
        const unsigned hz0 = cz * P2,   hz1 = (cz + 1u) * P2;

        const float2* __restrict__ tab =
            reinterpret_cast<const float2*>(tables) + (size_t)L * TABLE_SIZE;

        const float ox = 1.0f - wx, oy = 1.0f - wy, oz = 1.0f - wz;

        float ax = 0.0f, ay = 0.0f;
        #pragma unroll
        for (int c = 0; c < 8; c++) {
            const unsigned h = ((c & 1) ? hx1 : hx0)
                             ^ ((c & 2) ? hy1 : hy0)
                             ^ ((c & 4) ? hz1 : hz0);
            const unsigned idx = h & TMASK;
            const float2 t = __ldg(&tab[idx]);
            const float wc = ((c & 1) ? wx : ox)
                           * ((c & 2) ? wy : oy)
                           * ((c & 4) ? wz : oz);
            ax = fmaf(wc, t.x, ax);
            ay = fmaf(wc, t.y, ay);
        }
        a[2 * L + 0] = ax;
        a[2 * L + 1] = ay;
    }

    // ---- layer 1: [32] -> [64] packed as 32 f32x2 pairs over j ----
    ull h1p[32];
    #pragma unroll
    for (int j = 0; j < 32; j++)
        h1p[j] = *reinterpret_cast<const ull*>(&sB1[2 * j]);

    #pragma unroll
    for (int i = 0; i < 32; i++) {
        const ull ap = pack2(a[i], a[i]);
        const ull* wrow = reinterpret_cast<const ull*>(&sW1[i * 64]);
        #pragma unroll
        for (int j = 0; j < 32; j += 2) {
            const ulonglong2 w = *reinterpret_cast<const ulonglong2*>(&wrow[j]);
            h1p[j + 0] = fma2(ap, w.x, h1p[j + 0]);
            h1p[j + 1] = fma2(ap, w.y, h1p[j + 1]);
        }
    }

    // ---- layer 2: [64] -> [64] (packed over j, two halves), fused layer 3 ----
    float r3 = sB3;
    #pragma unroll
    for (int half = 0; half < 2; half++) {
        const int cb = 32 * half;
        ull acc[16];
        #pragma unroll
        for (int jj = 0; jj < 16; jj++)
            acc[jj] = *reinterpret_cast<const ull*>(&sB2[cb + 2 * jj]);

        #pragma unroll
        for (int i2 = 0; i2 < 32; i2++) {
            float lo, hi;
            unpack2(h1p[i2], lo, hi);
            lo = fmaxf(lo, 0.0f);
            hi = fmaxf(hi, 0.0f);
            const ull plo = pack2(lo, lo);
            const ull phi = pack2(hi, hi);
            const ull* w0 = reinterpret_cast<const ull*>(&sW2[(2 * i2 + 0) * 64 + cb]);
            const ull* w1 = reinterpret_cast<const ull*>(&sW2[(2 * i2 + 1) * 64 + cb]);
            #pragma unroll
            for (int jj = 0; jj < 16; jj += 2) {
                const ulonglong2 wa = *reinterpret_cast<const ulonglong2*>(&w0[jj]);
                acc[jj + 0] = fma2(plo, wa.x, acc[jj + 0]);
                acc[jj + 1] = fma2(plo, wa.y, acc[jj + 1]);
            }
            #pragma unroll
            for (int jj = 0; jj < 16; jj += 2) {
                const ulonglong2 wb = *reinterpret_cast<const ulonglong2*>(&w1[jj]);
                acc[jj + 0] = fma2(phi, wb.x, acc[jj + 0]);
                acc[jj + 1] = fma2(phi, wb.y, acc[jj + 1]);
            }
        }
        #pragma unroll
        for (int jj = 0; jj < 16; jj++) {
            float a0, a1;
            unpack2(acc[jj], a0, a1);
            r3 = fmaf(fmaxf(a0, 0.0f), sW3[cb + 2 * jj + 0], r3);
            r3 = fmaf(fmaxf(a1, 0.0f), sW3[cb + 2 * jj + 1], r3);
        }
    }

    out[oidx] = r3;
}

extern "C" void kernel_launch(void* const* d_in, const int* in_sizes, int n_in,
                              void* d_out, int out_size)
{
    const float* x    = (const float*)d_in[0];
    const float* tabs = (const float*)d_in[1];
    const float* res  = (const float*)d_in[2];
    const float* W1   = (const float*)d_in[3];
    const float* b1   = (const float*)d_in[4];
    const float* W2   = (const float*)d_in[5];
    const float* b2   = (const float*)d_in[6];
    const float* W3   = (const float*)d_in[7];
    const float* b3   = (const float*)d_in[8];
    float* out = (float*)d_out;

    const int n = in_sizes[0] / 3;

    k_zero<<<(NCELLS + 1023) / 1024, 1024>>>();
    k_hist<<<(n + 255) / 256, 256>>>(x, n);
    k_scan<<<1, SCAN_T>>>();
    k_scatter<<<(n + 255) / 256, 256>>>(x, n);

    const int grid = (n + BLOCK - 1) / BLOCK;
    hashgrid_mlp_kernel<<<grid, BLOCK>>>(tabs, res, W1, b1, W2, b2, W3, b3, out, n);
}

// round 8
// speedup vs baseline: 1.4855x; 1.4855x over previous
#include <cuda_runtime.h>
#include <cstdint>

#define N_LEVELS 16
#define TABLE_SIZE (1u << 19)
#define TMASK (TABLE_SIZE - 1u)
#define P1 2654435761u
#define P2 805459861u
#define BLOCK 128
#define MAXN 2000000
#define GBITS 6
#define GRES (1 << GBITS)            // 64 cells per dim
#define NCELLS (GRES * GRES * GRES)  // 262144
#define S1_T 1024                    // cells per scan1 block
#define S1_B (NCELLS / S1_T)         // 256 scan1 blocks

using ull = unsigned long long;

__device__ __forceinline__ ull pack2(float lo, float hi) {
    ull r; asm("mov.b64 %0, {%1, %2};" : "=l"(r) : "f"(lo), "f"(hi)); return r;
}
__device__ __forceinline__ void unpack2(ull v, float& lo, float& hi) {
    asm("mov.b64 {%0, %1}, %2;" : "=f"(lo), "=f"(hi) : "l"(v));
}
__device__ __forceinline__ ull fma2(ull a, ull b, ull c) {
    ull d; asm("fma.rn.f32x2 %0, %1, %2, %3;" : "=l"(d) : "l"(a), "l"(b), "l"(c)); return d;
}

// ---- static scratch (no allocation) ----
__device__ int    d_hist[NCELLS];
__device__ int    d_offs[NCELLS];
__device__ int    d_bsum[S1_B];
__device__ int    d_boff[S1_B];
__device__ float4 d_xs[MAXN];   // bucket-sorted: (x01, y01, z01, bits(orig_idx))

// Morton: interleave 2 zero bits between bits of v
__device__ __forceinline__ unsigned part1by2(unsigned v) {
    v &= 0x3FFu;
    v = (v | (v << 16)) & 0x030000FFu;
    v = (v | (v << 8))  & 0x0300F00Fu;
    v = (v | (v << 4))  & 0x030C30C3u;
    v = (v | (v << 2))  & 0x09249249u;
    return v;
}

__device__ __forceinline__ int cell_of(float x0, float x1, float x2) {
    unsigned cx = min(GRES - 1, (int)(x0 * (float)GRES));
    unsigned cy = min(GRES - 1, (int)(x1 * (float)GRES));
    unsigned cz = min(GRES - 1, (int)(x2 * (float)GRES));
    return (int)((part1by2(cx) << 2) | (part1by2(cy) << 1) | part1by2(cz));
}

__global__ void k_zero() {
    int i = blockIdx.x * blockDim.x + threadIdx.x;
    if (i < NCELLS) d_hist[i] = 0;
}

__global__ void k_hist(const float* __restrict__ x, int n) {
    int i = blockIdx.x * blockDim.x + threadIdx.x;
    if (i >= n) return;
    float x0 = x[3 * i + 0] * 0.5f + 0.5f;
    float x1 = x[3 * i + 1] * 0.5f + 0.5f;
    float x2 = x[3 * i + 2] * 0.5f + 0.5f;
    atomicAdd(&d_hist[cell_of(x0, x1, x2)], 1);
}

// phase 1: per-block scan of 1024 consecutive cells (coalesced), exclusive
// within block; block total -> d_bsum
__global__ void k_scan1() {
    __shared__ int sc[S1_T];
    const int t = threadIdx.x;
    const int g = blockIdx.x * S1_T + t;
    const int v = d_hist[g];
    sc[t] = v;
    __syncthreads();
    #pragma unroll
    for (int d = 1; d < S1_T; d <<= 1) {
        int u = (t >= d) ? sc[t - d] : 0;
        __syncthreads();
        sc[t] += u;
        __syncthreads();
    }
    d_offs[g] = sc[t] - v;                 // exclusive within block
    if (t == S1_T - 1) d_bsum[blockIdx.x] = sc[t];
}

// phase 2: exclusive scan of the 256 block totals
__global__ void k_scan2() {
    __shared__ int sc[S1_B];
    const int t = threadIdx.x;
    const int v = d_bsum[t];
    sc[t] = v;
    __syncthreads();
    #pragma unroll
    for (int d = 1; d < S1_B; d <<= 1) {
        int u = (t >= d) ? sc[t - d] : 0;
        __syncthreads();
        sc[t] += u;
        __syncthreads();
    }
    d_boff[t] = sc[t] - v;
}

// phase 3: add block offsets (coalesced)
__global__ void k_scan3() {
    const int g = blockIdx.x * S1_T + threadIdx.x;
    d_offs[g] += d_boff[blockIdx.x];
}

__global__ void k_scatter(const float* __restrict__ x, int n) {
    int i = blockIdx.x * blockDim.x + threadIdx.x;
    if (i >= n) return;
    float x0 = x[3 * i + 0] * 0.5f + 0.5f;
    float x1 = x[3 * i + 1] * 0.5f + 0.5f;
    float x2 = x[3 * i + 2] * 0.5f + 0.5f;
    int pos = atomicAdd(&d_offs[cell_of(x0, x1, x2)], 1);
    d_xs[pos] = make_float4(x0, x1, x2, __int_as_float(i));
}

__global__ __launch_bounds__(BLOCK, 4)
void hashgrid_mlp_kernel(const float* __restrict__ tables,
                         const float* __restrict__ resolutions,
                         const float* __restrict__ W1, const float* __restrict__ b1,
                         const float* __restrict__ W2, const float* __restrict__ b2,
                         const float* __restrict__ W3, const float* __restrict__ b3,
                         float* __restrict__ out, int n)
{
    __shared__ __align__(16) float sW1[32 * 64];
    __shared__ __align__(16) float sW2[64 * 64];
    __shared__ __align__(16) float sB1[64];
    __shared__ __align__(16) float sB2[64];
    __shared__ __align__(16) float sW3[64];
    __shared__ float sRes[16];
    __shared__ float sB3;

    const int tid = threadIdx.x;
    for (int i = tid; i < 32 * 64; i += BLOCK) sW1[i] = W1[i];
    for (int i = tid; i < 64 * 64; i += BLOCK) sW2[i] = W2[i];
    if (tid < 64) { sB1[tid] = b1[tid]; sB2[tid] = b2[tid]; sW3[tid] = W3[tid]; }
    if (tid < 16) sRes[tid] = resolutions[tid];
    if (tid == 0) sB3 = b3[0];
    __syncthreads();

    const int p = blockIdx.x * BLOCK + tid;
    if (p >= n) return;

    const float4 xi = d_xs[p];            // coalesced; Morton-bucket-sorted point
    const float x0 = xi.x, x1 = xi.y, x2 = xi.z;
    const int oidx = __float_as_int(xi.w);

    float a[2 * N_LEVELS];

    #pragma unroll
    for (int L = 0; L < N_LEVELS; L++) {
        const float r = sRes[L];
        const float px = x0 * r, py = x1 * r, pz = x2 * r;
        const float fx = floorf(px), fy = floorf(py), fz = floorf(pz);
        const float wx = px - fx, wy = py - fy, wz = pz - fz;
        const unsigned cx = (unsigned)fx, cy = (unsigned)fy, cz = (unsigned)fz;

        const unsigned hx0 = cx,        hx1 = cx + 1u;
        const unsigned hy0 = cy * P1,   hy1 = (cy + 1u) * P1;
        const unsigned hz0 = cz * P2,   hz1 = (cz + 1u) * P2;

        const float2* __restrict__ tab =
            reinterpret_cast<const float2*>(tables) + (size_t)L * TABLE_SIZE;

        const float ox = 1.0f - wx, oy = 1.0f - wy, oz = 1.0f - wz;

        float ax = 0.0f, ay = 0.0f;
        #pragma unroll
        for (int c = 0; c < 8; c++) {
            const unsigned h = ((c & 1) ? hx1 : hx0)
                             ^ ((c & 2) ? hy1 : hy0)
                             ^ ((c & 4) ? hz1 : hz0);
            const unsigned idx = h & TMASK;
            const float2 t = __ldg(&tab[idx]);
            const float wc = ((c & 1) ? wx : ox)
                           * ((c & 2) ? wy : oy)
                           * ((c & 4) ? wz : oz);
            ax = fmaf(wc, t.x, ax);
            ay = fmaf(wc, t.y, ay);
        }
        a[2 * L + 0] = ax;
        a[2 * L + 1] = ay;
    }

    // ---- layer 1: [32] -> [64] packed as 32 f32x2 pairs over j ----
    ull h1p[32];
    #pragma unroll
    for (int j = 0; j < 32; j++)
        h1p[j] = *reinterpret_cast<const ull*>(&sB1[2 * j]);

    #pragma unroll
    for (int i = 0; i < 32; i++) {
        const ull ap = pack2(a[i], a[i]);
        const ull* wrow = reinterpret_cast<const ull*>(&sW1[i * 64]);
        #pragma unroll
        for (int j = 0; j < 32; j += 2) {
            const ulonglong2 w = *reinterpret_cast<const ulonglong2*>(&wrow[j]);
            h1p[j + 0] = fma2(ap, w.x, h1p[j + 0]);
            h1p[j + 1] = fma2(ap, w.y, h1p[j + 1]);
        }
    }

    // ---- layer 2: [64] -> [64] (packed over j, two halves), fused layer 3 ----
    float r3 = sB3;
    #pragma unroll
    for (int half = 0; half < 2; half++) {
        const int cb = 32 * half;
        ull acc[16];
        #pragma unroll
        for (int jj = 0; jj < 16; jj++)
            acc[jj] = *reinterpret_cast<const ull*>(&sB2[cb + 2 * jj]);

        #pragma unroll
        for (int i2 = 0; i2 < 32; i2++) {
            float lo, hi;
            unpack2(h1p[i2], lo, hi);
            lo = fmaxf(lo, 0.0f);
            hi = fmaxf(hi, 0.0f);
            const ull plo = pack2(lo, lo);
            const ull phi = pack2(hi, hi);
            const ull* w0 = reinterpret_cast<const ull*>(&sW2[(2 * i2 + 0) * 64 + cb]);
            const ull* w1 = reinterpret_cast<const ull*>(&sW2[(2 * i2 + 1) * 64 + cb]);
            #pragma unroll
            for (int jj = 0; jj < 16; jj += 2) {
                const ulonglong2 wa = *reinterpret_cast<const ulonglong2*>(&w0[jj]);
                acc[jj + 0] = fma2(plo, wa.x, acc[jj + 0]);
                acc[jj + 1] = fma2(plo, wa.y, acc[jj + 1]);
            }
            #pragma unroll
            for (int jj = 0; jj < 16; jj += 2) {
                const ulonglong2 wb = *reinterpret_cast<const ulonglong2*>(&w1[jj]);
                acc[jj + 0] = fma2(phi, wb.x, acc[jj + 0]);
                acc[jj + 1] = fma2(phi, wb.y, acc[jj + 1]);
            }
        }
        #pragma unroll
        for (int jj = 0; jj < 16; jj++) {
            float a0, a1;
            unpack2(acc[jj], a0, a1);
            r3 = fmaf(fmaxf(a0, 0.0f), sW3[cb + 2 * jj + 0], r3);
            r3 = fmaf(fmaxf(a1, 0.0f), sW3[cb + 2 * jj + 1], r3);
        }
    }

    out[oidx] = r3;
}

extern "C" void kernel_launch(void* const* d_in, const int* in_sizes, int n_in,
                              void* d_out, int out_size)
{
    const float* x    = (const float*)d_in[0];
    const float* tabs = (const float*)d_in[1];
    const float* res  = (const float*)d_in[2];
    const float* W1   = (const float*)d_in[3];
    const float* b1   = (const float*)d_in[4];
    const float* W2   = (const float*)d_in[5];
    const float* b2   = (const float*)d_in[6];
    const float* W3   = (const float*)d_in[7];
    const float* b3   = (const float*)d_in[8];
    float* out = (float*)d_out;

    const int n = in_sizes[0] / 3;

    k_zero<<<(NCELLS + 1023) / 1024, 1024>>>();
    k_hist<<<(n + 255) / 256, 256>>>(x, n);
    k_scan1<<<S1_B, S1_T>>>();
    k_scan2<<<1, S1_B>>>();
    k_scan3<<<S1_B, S1_T>>>();
    k_scatter<<<(n + 255) / 256, 256>>>(x, n);

    const int grid = (n + BLOCK - 1) / BLOCK;
    hashgrid_mlp_kernel<<<grid, BLOCK>>>(tabs, res, W1, b1, W2, b2, W3, b3, out, n);
}